// round 14
// baseline (speedup 1.0000x reference)
#include <cuda_runtime.h>
#include <cuda_fp16.h>
#include <cstdint>

constexpr int S  = 24;
constexpr int Bn = 256;
constexpr int Dm = 1024;
constexpr int Ln = 12;
constexpr int Vn = 32000;
constexpr int Mr = S * Bn;          // 6144
constexpr int WROWS = Ln * 3 * Dm;  // 36864

// logits GEMM (proven 128x128 core)
constexpr int BM = 128, BN = 128, BK = 64, STAGES = 3;
constexpr int STAGE_BYTES = (BM * BK + BN * BK) * 2;      // 32 KB
constexpr int SMEM_BYTES  = STAGES * STAGE_BYTES;         // 96 KB

// fused layer kernel: 96x192 tile
constexpr int FST_BYTES = (96 * 64 + 192 * 64) * 2;       // 36864
constexpr int FSMEM = 3 * FST_BYTES;                      // 110592
constexpr int LQH = 33;   // q/k smem row stride in half2 (odd -> conflict-free)
constexpr int LQV = 68;   // v smem row stride in floats (16B-aligned)

// ---------------- scratch (device globals; no allocation) ----------------
// x rows are [b][s]: row = b*24 + s
__device__ float g_x[(size_t)Mr * Dm];
__device__ uint16_t g_xh16a[(size_t)Mr * Dm];  // fp16 x ping
__device__ uint16_t g_xh16b[(size_t)Mr * Dm];  // fp16 x pong
__device__ uint16_t g_w16[(size_t)WROWS * Dm]; // [l][h][q64|k64|v64][1024]
__device__ uint16_t g_ow16[(size_t)Vn * Dm];   // fp16 out_w

__device__ __forceinline__ uint32_t smem_u32(const void* p) {
    uint32_t a;
    asm("{ .reg .u64 t; cvta.to.shared.u64 t, %1; cvt.u32.u64 %0, t; }" : "=r"(a) : "l"(p));
    return a;
}

// xor swizzle for 128-byte rows: 16B chunk index xored with row%8
__device__ __forceinline__ uint32_t swz(int row, int g) {
    return (uint32_t)(row * 128 + ((g ^ (row & 7)) << 4));
}

// ---------------------------------------------------------------------------
// Fused layer kernel: grid (64 mT, 16 h), 256 threads (8 warps: 2m x 4n).
//   GEMM:  [96 rows of x] . [q|k|v weight slice of head h]^T -> 96x192
//   then in-block attention for 4 batches + residual + fp16 convert.
// ---------------------------------------------------------------------------
__global__ void __launch_bounds__(256, 2) layer_fused2(
    int parity, int layer,
    const float* __restrict__ qb, const float* __restrict__ kb,
    const float* __restrict__ vb)
{
    extern __shared__ char smem[];
    const uint32_t sb = smem_u32(smem);
    const int tid = threadIdx.x;
    const int lane = tid & 31;
    const int wid = tid >> 5;
    const int wm = wid & 1;
    const int wn = wid >> 1;
    const int mT = blockIdx.x;
    const int h  = blockIdx.y;

    const uint16_t* Xin = parity ? g_xh16b : g_xh16a;
    uint16_t* Xout      = parity ? g_xh16a : g_xh16b;
    const uint16_t* A = Xin + (size_t)mT * 96 * Dm;
    const uint16_t* W = g_w16 + ((size_t)layer * 16 + h) * 192 * Dm;

    auto loadStage = [&](int it, int slot) {
        const int k0 = it * 64;
        const uint32_t sa = sb + slot * FST_BYTES;
        const uint32_t sw = sa + 96 * 64 * 2;
#pragma unroll
        for (int i = 0; i < 3; i++) {              // A: 768 16B chunks
            int ch = tid + i * 256;
            int r = ch >> 3, cb = ch & 7;
            const void* gp = A + (size_t)r * Dm + k0 + cb * 8;
            asm volatile("cp.async.cg.shared.global [%0], [%1], 16;"
                         :: "r"(sa + swz(r, cb)), "l"(gp));
        }
#pragma unroll
        for (int i = 0; i < 6; i++) {              // W: 1536 16B chunks
            int ch = tid + i * 256;
            int r = ch >> 3, cb = ch & 7;
            const void* gp = W + (size_t)r * Dm + k0 + cb * 8;
            asm volatile("cp.async.cg.shared.global [%0], [%1], 16;"
                         :: "r"(sw + swz(r, cb)), "l"(gp));
        }
        asm volatile("cp.async.commit_group;");
    };

    float acc[3][6][4];
#pragma unroll
    for (int a = 0; a < 3; a++)
#pragma unroll
        for (int b = 0; b < 6; b++)
#pragma unroll
            for (int c = 0; c < 4; c++) acc[a][b][c] = 0.f;

    loadStage(0, 0);
    loadStage(1, 1);

    for (int it = 0; it < 16; it++) {
        if (it + 2 < 16) asm volatile("cp.async.wait_group 1;");
        else             asm volatile("cp.async.wait_group 0;");
        __syncthreads();
        if (it + 2 < 16) loadStage(it + 2, (it + 2) % 3);

        const uint32_t sa = sb + (it % 3) * FST_BYTES;
        const uint32_t sw = sa + 96 * 64 * 2;
#pragma unroll
        for (int q = 0; q < 4; q++) {
            uint32_t afr[3][4], bfr[6][2];
#pragma unroll
            for (int mi = 0; mi < 3; mi++) {
                int m = wm * 48 + mi * 16 + (lane & 15);
                int g = 2 * q + (lane >> 4);
                asm volatile("ldmatrix.sync.aligned.m8n8.x4.shared.b16 {%0,%1,%2,%3}, [%4];"
                             : "=r"(afr[mi][0]), "=r"(afr[mi][1]),
                               "=r"(afr[mi][2]), "=r"(afr[mi][3])
                             : "r"(sa + swz(m, g)));
            }
#pragma unroll
            for (int njp = 0; njp < 3; njp++) {
                int n = wn * 48 + njp * 16 + (lane & 7) + ((lane & 16) >> 1);
                int g = 2 * q + ((lane >> 3) & 1);
                asm volatile("ldmatrix.sync.aligned.m8n8.x4.shared.b16 {%0,%1,%2,%3}, [%4];"
                             : "=r"(bfr[2 * njp][0]), "=r"(bfr[2 * njp][1]),
                               "=r"(bfr[2 * njp + 1][0]), "=r"(bfr[2 * njp + 1][1])
                             : "r"(sw + swz(n, g)));
            }
#pragma unroll
            for (int mi = 0; mi < 3; mi++)
#pragma unroll
                for (int nj = 0; nj < 6; nj++) {
                    asm volatile(
                        "mma.sync.aligned.m16n8k16.row.col.f32.f16.f16.f32 "
                        "{%0,%1,%2,%3}, {%4,%5,%6,%7}, {%8,%9}, {%0,%1,%2,%3};"
                        : "+f"(acc[mi][nj][0]), "+f"(acc[mi][nj][1]),
                          "+f"(acc[mi][nj][2]), "+f"(acc[mi][nj][3])
                        : "r"(afr[mi][0]), "r"(afr[mi][1]),
                          "r"(afr[mi][2]), "r"(afr[mi][3]),
                          "r"(bfr[nj][0]), "r"(bfr[nj][1]));
                }
        }
    }
    __syncthreads();   // all warps done with stage smem; reuse it below

    // ---- scatter q/k (fp16 half2) and v (fp32) + bias to smem ----
    __half2* Qh = reinterpret_cast<__half2*>(smem);      // [96][LQH]
    __half2* Kh = Qh + 96 * LQH;
    float* Vs   = reinterpret_cast<float*>(Kh + 96 * LQH);   // [96][LQV]
    float* sc   = Vs + 96 * LQV;                         // [4][24][24]

    const int rl = lane >> 2;
    const int cl = 2 * (lane & 3);
#pragma unroll
    for (int mi = 0; mi < 3; mi++)
#pragma unroll
        for (int ro = 0; ro < 2; ro++) {
            int row = wm * 48 + mi * 16 + ro * 8 + rl;
#pragma unroll
            for (int nj = 0; nj < 6; nj++) {
                int c = wn * 48 + nj * 8 + cl;
                int mat = c >> 6;
                int cc = c & 63;
                const float* bp = (mat == 0) ? qb : (mat == 1) ? kb : vb;
                float v0 = acc[mi][nj][ro * 2 + 0] + bp[h * 64 + cc];
                float v1 = acc[mi][nj][ro * 2 + 1] + bp[h * 64 + cc + 1];
                if (mat == 2) {
                    Vs[row * LQV + cc]     = v0;
                    Vs[row * LQV + cc + 1] = v1;
                } else {
                    ((mat == 0) ? Qh : Kh)[row * LQH + (cc >> 1)] =
                        __floats2half2_rn(v0, v1);
                }
            }
        }
    __syncthreads();

    // ---- scores: 4 batches x 24 x 24, half2 inputs fp32 accum ----
    constexpr float scale = 0.03125f;   // 1/sqrt(1024)
    for (int p = tid; p < 2304; p += 256) {
        int bb = p / 576;
        int rem = p - bb * 576;
        int si = rem / 24, tj = rem - si * 24;
        const __half2* qrow = Qh + (bb * 24 + si) * LQH;
        const __half2* krow = Kh + (bb * 24 + tj) * LQH;
        float a = 0.f;
#pragma unroll
        for (int j = 0; j < 32; j++) {
            float2 q = __half22float2(qrow[j]);
            float2 k = __half22float2(krow[j]);
            a = fmaf(q.x, k.x, fmaf(q.y, k.y, a));
        }
        sc[p] = a * scale;
    }
    __syncthreads();

    // ---- softmax: 96 rows of 24; warp wid handles rows wid*12..+12 ----
#pragma unroll
    for (int rr = 0; rr < 12; rr++) {
        int r = wid * 12 + rr;
        float v = (lane < S) ? sc[r * 24 + lane] : -1e30f;
        float mx = v;
#pragma unroll
        for (int o = 16; o; o >>= 1) mx = fmaxf(mx, __shfl_xor_sync(0xFFFFFFFFu, mx, o));
        float e = (lane < S) ? expf(v - mx) : 0.f;
        float sum = e;
#pragma unroll
        for (int o = 16; o; o >>= 1) sum += __shfl_xor_sync(0xFFFFFFFFu, sum, o);
        if (lane < S) sc[r * 24 + lane] = e * (1.f / sum);
    }
    __syncthreads();

    // ---- AV + residual + fp16 convert, d8-blocked (768 tasks, 3/thread) ----
    for (int p = tid; p < 768; p += 256) {
        int bbsi = p >> 3;            // 0..95 (bb*24+si)
        int dg   = p & 7;             // 8-float group
        const float* scrow = sc + bbsi * 24;
        float4 o0 = make_float4(0.f, 0.f, 0.f, 0.f);
        float4 o1 = make_float4(0.f, 0.f, 0.f, 0.f);
#pragma unroll
        for (int t = 0; t < S; t++) {
            float wgt = scrow[t];
            const float* vr = Vs + ((bbsi / 24) * 24 + t) * LQV + dg * 8;
            float4 va = *reinterpret_cast<const float4*>(vr);
            float4 vb2 = *reinterpret_cast<const float4*>(vr + 4);
            o0.x = fmaf(wgt, va.x, o0.x);  o0.y = fmaf(wgt, va.y, o0.y);
            o0.z = fmaf(wgt, va.z, o0.z);  o0.w = fmaf(wgt, va.w, o0.w);
            o1.x = fmaf(wgt, vb2.x, o1.x); o1.y = fmaf(wgt, vb2.y, o1.y);
            o1.z = fmaf(wgt, vb2.z, o1.z); o1.w = fmaf(wgt, vb2.w, o1.w);
        }
        int rg = mT * 96 + bbsi;
        size_t off = (size_t)rg * Dm + h * 64 + dg * 8;
        float4 x0 = *reinterpret_cast<const float4*>(g_x + off);
        float4 x1 = *reinterpret_cast<const float4*>(g_x + off + 4);
        x0.x += o0.x; x0.y += o0.y; x0.z += o0.z; x0.w += o0.w;
        x1.x += o1.x; x1.y += o1.y; x1.z += o1.z; x1.w += o1.w;
        *reinterpret_cast<float4*>(g_x + off)     = x0;
        *reinterpret_cast<float4*>(g_x + off + 4) = x1;
        *reinterpret_cast<__half2*>(Xout + off)     = __floats2half2_rn(x0.x, x0.y);
        *reinterpret_cast<__half2*>(Xout + off + 2) = __floats2half2_rn(x0.z, x0.w);
        *reinterpret_cast<__half2*>(Xout + off + 4) = __floats2half2_rn(x1.x, x1.y);
        *reinterpret_cast<__half2*>(Xout + off + 6) = __floats2half2_rn(x1.z, x1.w);
    }
}

// ---------------------------------------------------------------------------
// Logits GEMM (128x128 proven core; A rows are [b][s], output rows [s][b])
// ---------------------------------------------------------------------------
__global__ void __launch_bounds__(256, 2) gemm_out_tc(
    const float* __restrict__ ob, float* __restrict__ out)
{
    const int mT = blockIdx.x, nT = blockIdx.y;
    const uint16_t* A = g_xh16a + (size_t)mT * 128 * Dm;
    const uint16_t* W = g_ow16 + (size_t)nT * 128 * Dm;
    const float* bias = ob + nT * 128;

    extern __shared__ char smem[];
    const uint32_t sb = smem_u32(smem);
    const int tid = threadIdx.x;
    const int lane = tid & 31;
    const int wid = tid >> 5;
    const int wm = wid & 3;
    const int wn = wid >> 2;

    auto loadStage = [&](int it, int slot) {
        const int k0 = it * BK;
        const uint32_t sa = sb + slot * STAGE_BYTES;
        const uint32_t sw = sa + BM * BK * 2;
#pragma unroll
        for (int i = 0; i < 4; i++) {
            int ch = tid + i * 256;
            int r = ch >> 3, cb = ch & 7;
            const void* gp = A + (size_t)r * Dm + k0 + cb * 8;
            asm volatile("cp.async.cg.shared.global [%0], [%1], 16;"
                         :: "r"(sa + swz(r, cb)), "l"(gp));
        }
#pragma unroll
        for (int i = 0; i < 4; i++) {
            int ch = tid + i * 256;
            int r = ch >> 3, cb = ch & 7;
            const void* gp = W + (size_t)r * Dm + k0 + cb * 8;
            asm volatile("cp.async.cg.shared.global [%0], [%1], 16;"
                         :: "r"(sw + swz(r, cb)), "l"(gp));
        }
        asm volatile("cp.async.commit_group;");
    };

    float acc[2][8][4];
#pragma unroll
    for (int a = 0; a < 2; a++)
#pragma unroll
        for (int b = 0; b < 8; b++)
#pragma unroll
            for (int c = 0; c < 4; c++) acc[a][b][c] = 0.f;

    loadStage(0, 0);
    loadStage(1, 1);

    for (int it = 0; it < 16; it++) {
        if (it + 2 < 16) asm volatile("cp.async.wait_group 1;");
        else             asm volatile("cp.async.wait_group 0;");
        __syncthreads();
        if (it + 2 < 16) loadStage(it + 2, (it + 2) % STAGES);

        const uint32_t sa = sb + (it % STAGES) * STAGE_BYTES;
        const uint32_t sw = sa + BM * BK * 2;
#pragma unroll
        for (int q = 0; q < 4; q++) {
            uint32_t afr[2][4], bfr[8][2];
#pragma unroll
            for (int mi = 0; mi < 2; mi++) {
                int m = wm * 32 + mi * 16 + (lane & 15);
                int g = 2 * q + (lane >> 4);
                asm volatile("ldmatrix.sync.aligned.m8n8.x4.shared.b16 {%0,%1,%2,%3}, [%4];"
                             : "=r"(afr[mi][0]), "=r"(afr[mi][1]),
                               "=r"(afr[mi][2]), "=r"(afr[mi][3])
                             : "r"(sa + swz(m, g)));
            }
#pragma unroll
            for (int nj = 0; nj < 8; nj += 2) {
                int n = wn * 64 + nj * 8 + (lane & 7) + ((lane & 16) >> 1);
                int g = 2 * q + ((lane >> 3) & 1);
                asm volatile("ldmatrix.sync.aligned.m8n8.x4.shared.b16 {%0,%1,%2,%3}, [%4];"
                             : "=r"(bfr[nj][0]), "=r"(bfr[nj][1]),
                               "=r"(bfr[nj + 1][0]), "=r"(bfr[nj + 1][1])
                             : "r"(sw + swz(n, g)));
            }
#pragma unroll
            for (int mi = 0; mi < 2; mi++)
#pragma unroll
                for (int nj = 0; nj < 8; nj++) {
                    asm volatile(
                        "mma.sync.aligned.m16n8k16.row.col.f32.f16.f16.f32 "
                        "{%0,%1,%2,%3}, {%4,%5,%6,%7}, {%8,%9}, {%0,%1,%2,%3};"
                        : "+f"(acc[mi][nj][0]), "+f"(acc[mi][nj][1]),
                          "+f"(acc[mi][nj][2]), "+f"(acc[mi][nj][3])
                        : "r"(afr[mi][0]), "r"(afr[mi][1]),
                          "r"(afr[mi][2]), "r"(afr[mi][3]),
                          "r"(bfr[nj][0]), "r"(bfr[nj][1]));
                }
        }
    }

    const int r0 = wm * 32 + (lane >> 2);
    const int cl = 2 * (lane & 3);
#pragma unroll
    for (int mi = 0; mi < 2; mi++)
#pragma unroll
        for (int ro = 0; ro < 2; ro++) {
            int rg = mT * 128 + r0 + mi * 16 + ro * 8;     // [b][s] row
            int bb = rg / 24, ss = rg - bb * 24;
            float* crow = out + ((size_t)ss * Bn + bb) * Vn;
#pragma unroll
            for (int nj = 0; nj < 8; nj++) {
                int col = wn * 64 + nj * 8 + cl;
                float2 o;
                o.x = acc[mi][nj][ro * 2 + 0] + bias[col];
                o.y = acc[mi][nj][ro * 2 + 1] + bias[col + 1];
                *reinterpret_cast<float2*>(crow + nT * 128 + col) = o;
            }
        }
}

// ---------------------------------------------------------------------------
// Weight prep: qkv -> [l][h][q64|k64|v64][1024] fp16;  out_w -> fp16
// ---------------------------------------------------------------------------
__global__ void conv_wqkv16(const float* __restrict__ qw, const float* __restrict__ kw,
                            const float* __restrict__ vw) {
    size_t t = (size_t)blockIdx.x * 256 + threadIdx.x;
    size_t e = t * 4;
    int row = (int)(e >> 10);        // dest row in [l][h][192]
    int col = (int)(e & 1023);
    int l    = row / 3072;
    int rem  = row - l * 3072;
    int hh   = rem / 192;
    int rem2 = rem - hh * 192;
    int mat  = rem2 >> 6;
    int n    = hh * 64 + (rem2 & 63);
    const float* src = ((mat == 0) ? qw : (mat == 1) ? kw : vw)
                       + (((size_t)l * 1024 + n) << 10) + col;
    float4 v = *reinterpret_cast<const float4*>(src);
    size_t d = ((size_t)row << 10) + col;
    *reinterpret_cast<__half2*>(g_w16 + d)     = __floats2half2_rn(v.x, v.y);
    *reinterpret_cast<__half2*>(g_w16 + d + 2) = __floats2half2_rn(v.z, v.w);
}

__global__ void conv_wout16(const float* __restrict__ ow) {
    size_t e = ((size_t)blockIdx.x * 256 + threadIdx.x) * 4;
    float4 v = *reinterpret_cast<const float4*>(ow + e);
    *reinterpret_cast<__half2*>(g_ow16 + e)     = __floats2half2_rn(v.x, v.y);
    *reinterpret_cast<__half2*>(g_ow16 + e + 2) = __floats2half2_rn(v.z, v.w);
}

// ---------------------------------------------------------------------------
// Embedding into [b][s] layout + fp16 convert (buffer A)
// ---------------------------------------------------------------------------
__global__ void embed_kernel(const int* __restrict__ inputs,
                             const float* __restrict__ tok,
                             const float* __restrict__ pe) {
    int row = blockIdx.x;            // b*24 + s
    int b = row / 24;
    int s = row - b * 24;
    int t = inputs[s * Bn + b];
    const float4* te = reinterpret_cast<const float4*>(tok + (size_t)t * Dm);
    const float4* pp = reinterpret_cast<const float4*>(pe + (size_t)s * Dm);
    float4 a = te[threadIdx.x];
    float4 bp = pp[threadIdx.x];
    float4 o = make_float4(a.x + bp.x, a.y + bp.y, a.z + bp.z, a.w + bp.w);
    size_t d = (size_t)row * Dm + threadIdx.x * 4;
    *reinterpret_cast<float4*>(g_x + d) = o;
    *reinterpret_cast<__half2*>(g_xh16a + d)     = __floats2half2_rn(o.x, o.y);
    *reinterpret_cast<__half2*>(g_xh16a + d + 2) = __floats2half2_rn(o.z, o.w);
}

// ---------------------------------------------------------------------------
extern "C" void kernel_launch(void* const* d_in, const int* in_sizes, int n_in,
                              void* d_out, int out_size) {
    const int*   inputs = (const int*)d_in[0];
    // d_in[1] = mask (reference drops it)
    const float* tok = (const float*)d_in[2];
    const float* pe  = (const float*)d_in[3];
    const float* qw  = (const float*)d_in[4];
    const float* qb  = (const float*)d_in[5];
    const float* kw  = (const float*)d_in[6];
    const float* kb  = (const float*)d_in[7];
    const float* vw  = (const float*)d_in[8];
    const float* vb  = (const float*)d_in[9];
    const float* ow  = (const float*)d_in[10];
    const float* ob  = (const float*)d_in[11];
    float* out = (float*)d_out;

    cudaFuncSetAttribute(layer_fused2, cudaFuncAttributeMaxDynamicSharedMemorySize, FSMEM);
    cudaFuncSetAttribute(gemm_out_tc, cudaFuncAttributeMaxDynamicSharedMemorySize, SMEM_BYTES);

    conv_wqkv16<<<WROWS, 256>>>(qw, kw, vw);
    conv_wout16<<<Vn, 256>>>(ow);
    embed_kernel<<<Mr, 256>>>(inputs, tok, pe);

    for (int l = 0; l < Ln; l++) {
        layer_fused2<<<dim3(64, 16), 256, FSMEM>>>(
            l & 1, l, qb + (size_t)l * Dm, kb + (size_t)l * Dm, vb + (size_t)l * Dm);
    }
    gemm_out_tc<<<dim3(48, 250), 256, SMEM_BYTES>>>(ob, out);
}

// round 15
// speedup vs baseline: 1.0354x; 1.0354x over previous
#include <cuda_runtime.h>
#include <cuda_fp16.h>
#include <cstdint>

constexpr int S  = 24;
constexpr int Bn = 256;
constexpr int Dm = 1024;
constexpr int Ln = 12;
constexpr int Vn = 32000;
constexpr int Mr = S * Bn;          // 6144
constexpr int WROWS = Ln * 3 * Dm;  // 36864

// logits GEMM (proven 128x128 core)
constexpr int BM = 128, BN = 128, BK = 64, STAGES = 3;
constexpr int STAGE_BYTES = (BM * BK + BN * BK) * 2;      // 32 KB
constexpr int SMEM_BYTES  = STAGES * STAGE_BYTES;         // 96 KB

// fused layer kernel: 96x192 tile
constexpr int FST_BYTES = (96 * 64 + 192 * 64) * 2;       // 36864
constexpr int FSMEM = 3 * FST_BYTES;                      // 110592
constexpr int LQ = 68;                                    // q/k/v smem row stride

// ---------------- scratch (device globals; no allocation) ----------------
// x rows are [b][s]: row = b*24 + s
__device__ float g_x[(size_t)Mr * Dm];
__device__ uint16_t g_xh16a[(size_t)Mr * Dm];  // fp16 x ping
__device__ uint16_t g_xh16b[(size_t)Mr * Dm];  // fp16 x pong
__device__ uint16_t g_w16[(size_t)WROWS * Dm]; // [l][h][q64|k64|v64][1024]
__device__ uint16_t g_ow16[(size_t)Vn * Dm];   // fp16 out_w

__device__ __forceinline__ uint32_t smem_u32(const void* p) {
    uint32_t a;
    asm("{ .reg .u64 t; cvta.to.shared.u64 t, %1; cvt.u32.u64 %0, t; }" : "=r"(a) : "l"(p));
    return a;
}

// xor swizzle for 128-byte rows: 16B chunk index xored with row%8
__device__ __forceinline__ uint32_t swz(int row, int g) {
    return (uint32_t)(row * 128 + ((g ^ (row & 7)) << 4));
}

// ---------------------------------------------------------------------------
// Fused layer kernel: grid (64 mT, 16 h), 256 threads (8 warps: 2m x 4n).
//   GEMM:  [96 rows of x] . [q|k|v weight slice of head h]^T -> 96x192
//   then in-block attention for 4 batches + residual + fp16 convert.
// ---------------------------------------------------------------------------
__global__ void __launch_bounds__(256, 2) layer_fused2(
    int parity, int layer,
    const float* __restrict__ qb, const float* __restrict__ kb,
    const float* __restrict__ vb)
{
    extern __shared__ char smem[];
    const uint32_t sb = smem_u32(smem);
    const int tid = threadIdx.x;
    const int lane = tid & 31;
    const int wid = tid >> 5;
    const int wm = wid & 1;
    const int wn = wid >> 1;
    const int mT = blockIdx.x;
    const int h  = blockIdx.y;

    const uint16_t* Xin = parity ? g_xh16b : g_xh16a;
    uint16_t* Xout      = parity ? g_xh16a : g_xh16b;
    const uint16_t* A = Xin + (size_t)mT * 96 * Dm;
    const uint16_t* W = g_w16 + ((size_t)layer * 16 + h) * 192 * Dm;

    auto loadStage = [&](int it, int slot) {
        const int k0 = it * 64;
        const uint32_t sa = sb + slot * FST_BYTES;
        const uint32_t sw = sa + 96 * 64 * 2;
#pragma unroll
        for (int i = 0; i < 3; i++) {              // A: 768 16B chunks
            int ch = tid + i * 256;
            int r = ch >> 3, cb = ch & 7;
            const void* gp = A + (size_t)r * Dm + k0 + cb * 8;
            asm volatile("cp.async.cg.shared.global [%0], [%1], 16;"
                         :: "r"(sa + swz(r, cb)), "l"(gp));
        }
#pragma unroll
        for (int i = 0; i < 6; i++) {              // W: 1536 16B chunks
            int ch = tid + i * 256;
            int r = ch >> 3, cb = ch & 7;
            const void* gp = W + (size_t)r * Dm + k0 + cb * 8;
            asm volatile("cp.async.cg.shared.global [%0], [%1], 16;"
                         :: "r"(sw + swz(r, cb)), "l"(gp));
        }
        asm volatile("cp.async.commit_group;");
    };

    float acc[3][6][4];
#pragma unroll
    for (int a = 0; a < 3; a++)
#pragma unroll
        for (int b = 0; b < 6; b++)
#pragma unroll
            for (int c = 0; c < 4; c++) acc[a][b][c] = 0.f;

    loadStage(0, 0);
    loadStage(1, 1);

    for (int it = 0; it < 16; it++) {
        if (it + 2 < 16) asm volatile("cp.async.wait_group 1;");
        else             asm volatile("cp.async.wait_group 0;");
        __syncthreads();
        if (it + 2 < 16) loadStage(it + 2, (it + 2) % 3);

        const uint32_t sa = sb + (it % 3) * FST_BYTES;
        const uint32_t sw = sa + 96 * 64 * 2;
#pragma unroll
        for (int q = 0; q < 4; q++) {
            uint32_t afr[3][4], bfr[6][2];
#pragma unroll
            for (int mi = 0; mi < 3; mi++) {
                int m = wm * 48 + mi * 16 + (lane & 15);
                int g = 2 * q + (lane >> 4);
                asm volatile("ldmatrix.sync.aligned.m8n8.x4.shared.b16 {%0,%1,%2,%3}, [%4];"
                             : "=r"(afr[mi][0]), "=r"(afr[mi][1]),
                               "=r"(afr[mi][2]), "=r"(afr[mi][3])
                             : "r"(sa + swz(m, g)));
            }
#pragma unroll
            for (int njp = 0; njp < 3; njp++) {
                int n = wn * 48 + njp * 16 + (lane & 7) + ((lane & 16) >> 1);
                int g = 2 * q + ((lane >> 3) & 1);
                asm volatile("ldmatrix.sync.aligned.m8n8.x4.shared.b16 {%0,%1,%2,%3}, [%4];"
                             : "=r"(bfr[2 * njp][0]), "=r"(bfr[2 * njp][1]),
                               "=r"(bfr[2 * njp + 1][0]), "=r"(bfr[2 * njp + 1][1])
                             : "r"(sw + swz(n, g)));
            }
#pragma unroll
            for (int mi = 0; mi < 3; mi++)
#pragma unroll
                for (int nj = 0; nj < 6; nj++) {
                    asm volatile(
                        "mma.sync.aligned.m16n8k16.row.col.f32.f16.f16.f32 "
                        "{%0,%1,%2,%3}, {%4,%5,%6,%7}, {%8,%9}, {%0,%1,%2,%3};"
                        : "+f"(acc[mi][nj][0]), "+f"(acc[mi][nj][1]),
                          "+f"(acc[mi][nj][2]), "+f"(acc[mi][nj][3])
                        : "r"(afr[mi][0]), "r"(afr[mi][1]),
                          "r"(afr[mi][2]), "r"(afr[mi][3]),
                          "r"(bfr[nj][0]), "r"(bfr[nj][1]));
                }
        }
    }
    __syncthreads();   // all warps done with stage smem; reuse it below

    // ---- scatter q/k/v (+bias) to smem, fp32 ----
    float* Qs = reinterpret_cast<float*>(smem);          // [96][LQ]
    float* Ks = Qs + 96 * LQ;
    float* Vs = Ks + 96 * LQ;
    float* sc = Vs + 96 * LQ;                            // [4][24][24]

    const int rl = lane >> 2;
    const int cl = 2 * (lane & 3);
#pragma unroll
    for (int mi = 0; mi < 3; mi++)
#pragma unroll
        for (int ro = 0; ro < 2; ro++) {
            int row = wm * 48 + mi * 16 + ro * 8 + rl;
#pragma unroll
            for (int nj = 0; nj < 6; nj++) {
                int c = wn * 48 + nj * 8 + cl;
                int mat = c >> 6;
                int cc = c & 63;
                const float* bp = (mat == 0) ? qb : (mat == 1) ? kb : vb;
                float* dst = ((mat == 0) ? Qs : (mat == 1) ? Ks : Vs) + row * LQ + cc;
                dst[0] = acc[mi][nj][ro * 2 + 0] + bp[h * 64 + cc];
                dst[1] = acc[mi][nj][ro * 2 + 1] + bp[h * 64 + cc + 1];
            }
        }
    __syncthreads();

    // ---- scores: 768 tasks, 3 si per task sharing the k-row ----
    constexpr float scale = 0.03125f;   // 1/sqrt(1024)
    for (int p = tid; p < 768; p += 256) {
        int bb  = p / 192;
        int rem = p - bb * 192;
        int sg  = rem / 24;              // si triple: rows sg*3..sg*3+2
        int tj  = rem - sg * 24;
        int si0 = sg * 3;
        const float* krow = Ks + (bb * 24 + tj) * LQ;
        float a0 = 0.f, a1 = 0.f, a2 = 0.f;
#pragma unroll
        for (int d4 = 0; d4 < 16; d4++) {
            float4 kv = *reinterpret_cast<const float4*>(krow + d4 * 4);
            float4 q0 = *reinterpret_cast<const float4*>(Qs + (bb * 24 + si0 + 0) * LQ + d4 * 4);
            float4 q1 = *reinterpret_cast<const float4*>(Qs + (bb * 24 + si0 + 1) * LQ + d4 * 4);
            float4 q2 = *reinterpret_cast<const float4*>(Qs + (bb * 24 + si0 + 2) * LQ + d4 * 4);
            a0 = fmaf(q0.x, kv.x, fmaf(q0.y, kv.y, fmaf(q0.z, kv.z, fmaf(q0.w, kv.w, a0))));
            a1 = fmaf(q1.x, kv.x, fmaf(q1.y, kv.y, fmaf(q1.z, kv.z, fmaf(q1.w, kv.w, a1))));
            a2 = fmaf(q2.x, kv.x, fmaf(q2.y, kv.y, fmaf(q2.z, kv.z, fmaf(q2.w, kv.w, a2))));
        }
        sc[(bb * 24 + si0 + 0) * 24 + tj] = a0 * scale;
        sc[(bb * 24 + si0 + 1) * 24 + tj] = a1 * scale;
        sc[(bb * 24 + si0 + 2) * 24 + tj] = a2 * scale;
    }
    __syncthreads();

    // ---- softmax: 96 rows of 24; warp wid handles rows wid*12..+12 ----
#pragma unroll
    for (int rr = 0; rr < 12; rr++) {
        int r = wid * 12 + rr;
        float v = (lane < S) ? sc[r * 24 + lane] : -1e30f;
        float mx = v;
#pragma unroll
        for (int o = 16; o; o >>= 1) mx = fmaxf(mx, __shfl_xor_sync(0xFFFFFFFFu, mx, o));
        float e = (lane < S) ? expf(v - mx) : 0.f;
        float sum = e;
#pragma unroll
        for (int o = 16; o; o >>= 1) sum += __shfl_xor_sync(0xFFFFFFFFu, sum, o);
        if (lane < S) sc[r * 24 + lane] = e * (1.f / sum);
    }
    __syncthreads();

    // ---- AV + residual + fp16 convert, d8-blocked (768 tasks, 3/thread) ----
    for (int p = tid; p < 768; p += 256) {
        int bbsi = p >> 3;            // 0..95 (bb*24+si)
        int dg   = p & 7;             // 8-float group
        int bb   = bbsi / 24;
        const float* scrow = sc + bbsi * 24;
        float4 o0 = make_float4(0.f, 0.f, 0.f, 0.f);
        float4 o1 = make_float4(0.f, 0.f, 0.f, 0.f);
#pragma unroll
        for (int t = 0; t < S; t++) {
            float wgt = scrow[t];
            const float* vr = Vs + (bb * 24 + t) * LQ + dg * 8;
            float4 va  = *reinterpret_cast<const float4*>(vr);
            float4 vb2 = *reinterpret_cast<const float4*>(vr + 4);
            o0.x = fmaf(wgt, va.x, o0.x);  o0.y = fmaf(wgt, va.y, o0.y);
            o0.z = fmaf(wgt, va.z, o0.z);  o0.w = fmaf(wgt, va.w, o0.w);
            o1.x = fmaf(wgt, vb2.x, o1.x); o1.y = fmaf(wgt, vb2.y, o1.y);
            o1.z = fmaf(wgt, vb2.z, o1.z); o1.w = fmaf(wgt, vb2.w, o1.w);
        }
        int rg = mT * 96 + bbsi;
        size_t off = (size_t)rg * Dm + h * 64 + dg * 8;
        float4 x0 = *reinterpret_cast<const float4*>(g_x + off);
        float4 x1 = *reinterpret_cast<const float4*>(g_x + off + 4);
        x0.x += o0.x; x0.y += o0.y; x0.z += o0.z; x0.w += o0.w;
        x1.x += o1.x; x1.y += o1.y; x1.z += o1.z; x1.w += o1.w;
        *reinterpret_cast<float4*>(g_x + off)     = x0;
        *reinterpret_cast<float4*>(g_x + off + 4) = x1;
        *reinterpret_cast<__half2*>(Xout + off)     = __floats2half2_rn(x0.x, x0.y);
        *reinterpret_cast<__half2*>(Xout + off + 2) = __floats2half2_rn(x0.z, x0.w);
        *reinterpret_cast<__half2*>(Xout + off + 4) = __floats2half2_rn(x1.x, x1.y);
        *reinterpret_cast<__half2*>(Xout + off + 6) = __floats2half2_rn(x1.z, x1.w);
    }
}

// ---------------------------------------------------------------------------
// Logits GEMM (128x128 proven core; A rows are [b][s], output rows [s][b])
// ---------------------------------------------------------------------------
__global__ void __launch_bounds__(256, 2) gemm_out_tc(
    const float* __restrict__ ob, float* __restrict__ out)
{
    const int mT = blockIdx.x, nT = blockIdx.y;
    const uint16_t* A = g_xh16a + (size_t)mT * 128 * Dm;
    const uint16_t* W = g_ow16 + (size_t)nT * 128 * Dm;
    const float* bias = ob + nT * 128;

    extern __shared__ char smem[];
    const uint32_t sb = smem_u32(smem);
    const int tid = threadIdx.x;
    const int lane = tid & 31;
    const int wid = tid >> 5;
    const int wm = wid & 3;
    const int wn = wid >> 2;

    auto loadStage = [&](int it, int slot) {
        const int k0 = it * BK;
        const uint32_t sa = sb + slot * STAGE_BYTES;
        const uint32_t sw = sa + BM * BK * 2;
#pragma unroll
        for (int i = 0; i < 4; i++) {
            int ch = tid + i * 256;
            int r = ch >> 3, cb = ch & 7;
            const void* gp = A + (size_t)r * Dm + k0 + cb * 8;
            asm volatile("cp.async.cg.shared.global [%0], [%1], 16;"
                         :: "r"(sa + swz(r, cb)), "l"(gp));
        }
#pragma unroll
        for (int i = 0; i < 4; i++) {
            int ch = tid + i * 256;
            int r = ch >> 3, cb = ch & 7;
            const void* gp = W + (size_t)r * Dm + k0 + cb * 8;
            asm volatile("cp.async.cg.shared.global [%0], [%1], 16;"
                         :: "r"(sw + swz(r, cb)), "l"(gp));
        }
        asm volatile("cp.async.commit_group;");
    };

    float acc[2][8][4];
#pragma unroll
    for (int a = 0; a < 2; a++)
#pragma unroll
        for (int b = 0; b < 8; b++)
#pragma unroll
            for (int c = 0; c < 4; c++) acc[a][b][c] = 0.f;

    loadStage(0, 0);
    loadStage(1, 1);

    for (int it = 0; it < 16; it++) {
        if (it + 2 < 16) asm volatile("cp.async.wait_group 1;");
        else             asm volatile("cp.async.wait_group 0;");
        __syncthreads();
        if (it + 2 < 16) loadStage(it + 2, (it + 2) % STAGES);

        const uint32_t sa = sb + (it % STAGES) * STAGE_BYTES;
        const uint32_t sw = sa + BM * BK * 2;
#pragma unroll
        for (int q = 0; q < 4; q++) {
            uint32_t afr[2][4], bfr[8][2];
#pragma unroll
            for (int mi = 0; mi < 2; mi++) {
                int m = wm * 32 + mi * 16 + (lane & 15);
                int g = 2 * q + (lane >> 4);
                asm volatile("ldmatrix.sync.aligned.m8n8.x4.shared.b16 {%0,%1,%2,%3}, [%4];"
                             : "=r"(afr[mi][0]), "=r"(afr[mi][1]),
                               "=r"(afr[mi][2]), "=r"(afr[mi][3])
                             : "r"(sa + swz(m, g)));
            }
#pragma unroll
            for (int nj = 0; nj < 8; nj += 2) {
                int n = wn * 64 + nj * 8 + (lane & 7) + ((lane & 16) >> 1);
                int g = 2 * q + ((lane >> 3) & 1);
                asm volatile("ldmatrix.sync.aligned.m8n8.x4.shared.b16 {%0,%1,%2,%3}, [%4];"
                             : "=r"(bfr[nj][0]), "=r"(bfr[nj][1]),
                               "=r"(bfr[nj + 1][0]), "=r"(bfr[nj + 1][1])
                             : "r"(sw + swz(n, g)));
            }
#pragma unroll
            for (int mi = 0; mi < 2; mi++)
#pragma unroll
                for (int nj = 0; nj < 8; nj++) {
                    asm volatile(
                        "mma.sync.aligned.m16n8k16.row.col.f32.f16.f16.f32 "
                        "{%0,%1,%2,%3}, {%4,%5,%6,%7}, {%8,%9}, {%0,%1,%2,%3};"
                        : "+f"(acc[mi][nj][0]), "+f"(acc[mi][nj][1]),
                          "+f"(acc[mi][nj][2]), "+f"(acc[mi][nj][3])
                        : "r"(afr[mi][0]), "r"(afr[mi][1]),
                          "r"(afr[mi][2]), "r"(afr[mi][3]),
                          "r"(bfr[nj][0]), "r"(bfr[nj][1]));
                }
        }
    }

    const int r0 = wm * 32 + (lane >> 2);
    const int cl = 2 * (lane & 3);
#pragma unroll
    for (int mi = 0; mi < 2; mi++)
#pragma unroll
        for (int ro = 0; ro < 2; ro++) {
            int rg = mT * 128 + r0 + mi * 16 + ro * 8;     // [b][s] row
            int bb = rg / 24, ss = rg - bb * 24;
            float* crow = out + ((size_t)ss * Bn + bb) * Vn;
#pragma unroll
            for (int nj = 0; nj < 8; nj++) {
                int col = wn * 64 + nj * 8 + cl;
                float2 o;
                o.x = acc[mi][nj][ro * 2 + 0] + bias[col];
                o.y = acc[mi][nj][ro * 2 + 1] + bias[col + 1];
                *reinterpret_cast<float2*>(crow + nT * 128 + col) = o;
            }
        }
}

// ---------------------------------------------------------------------------
// Weight prep: qkv -> [l][h][q64|k64|v64][1024] fp16;  out_w -> fp16
// ---------------------------------------------------------------------------
__global__ void conv_wqkv16(const float* __restrict__ qw, const float* __restrict__ kw,
                            const float* __restrict__ vw) {
    size_t t = (size_t)blockIdx.x * 256 + threadIdx.x;
    size_t e = t * 4;
    int row = (int)(e >> 10);        // dest row in [l][h][192]
    int col = (int)(e & 1023);
    int l    = row / 3072;
    int rem  = row - l * 3072;
    int hh   = rem / 192;
    int rem2 = rem - hh * 192;
    int mat  = rem2 >> 6;
    int n    = hh * 64 + (rem2 & 63);
    const float* src = ((mat == 0) ? qw : (mat == 1) ? kw : vw)
                       + (((size_t)l * 1024 + n) << 10) + col;
    float4 v = *reinterpret_cast<const float4*>(src);
    size_t d = ((size_t)row << 10) + col;
    *reinterpret_cast<__half2*>(g_w16 + d)     = __floats2half2_rn(v.x, v.y);
    *reinterpret_cast<__half2*>(g_w16 + d + 2) = __floats2half2_rn(v.z, v.w);
}

__global__ void conv_wout16(const float* __restrict__ ow) {
    size_t e = ((size_t)blockIdx.x * 256 + threadIdx.x) * 4;
    float4 v = *reinterpret_cast<const float4*>(ow + e);
    *reinterpret_cast<__half2*>(g_ow16 + e)     = __floats2half2_rn(v.x, v.y);
    *reinterpret_cast<__half2*>(g_ow16 + e + 2) = __floats2half2_rn(v.z, v.w);
}

// ---------------------------------------------------------------------------
// Embedding into [b][s] layout + fp16 convert (buffer A)
// ---------------------------------------------------------------------------
__global__ void embed_kernel(const int* __restrict__ inputs,
                             const float* __restrict__ tok,
                             const float* __restrict__ pe) {
    int row = blockIdx.x;            // b*24 + s
    int b = row / 24;
    int s = row - b * 24;
    int t = inputs[s * Bn + b];
    const float4* te = reinterpret_cast<const float4*>(tok + (size_t)t * Dm);
    const float4* pp = reinterpret_cast<const float4*>(pe + (size_t)s * Dm);
    float4 a = te[threadIdx.x];
    float4 bp = pp[threadIdx.x];
    float4 o = make_float4(a.x + bp.x, a.y + bp.y, a.z + bp.z, a.w + bp.w);
    size_t d = (size_t)row * Dm + threadIdx.x * 4;
    *reinterpret_cast<float4*>(g_x + d) = o;
    *reinterpret_cast<__half2*>(g_xh16a + d)     = __floats2half2_rn(o.x, o.y);
    *reinterpret_cast<__half2*>(g_xh16a + d + 2) = __floats2half2_rn(o.z, o.w);
}

// ---------------------------------------------------------------------------
extern "C" void kernel_launch(void* const* d_in, const int* in_sizes, int n_in,
                              void* d_out, int out_size) {
    const int*   inputs = (const int*)d_in[0];
    // d_in[1] = mask (reference drops it)
    const float* tok = (const float*)d_in[2];
    const float* pe  = (const float*)d_in[3];
    const float* qw  = (const float*)d_in[4];
    const float* qb  = (const float*)d_in[5];
    const float* kw  = (const float*)d_in[6];
    const float* kb  = (const float*)d_in[7];
    const float* vw  = (const float*)d_in[8];
    const float* vb  = (const float*)d_in[9];
    const float* ow  = (const float*)d_in[10];
    const float* ob  = (const float*)d_in[11];
    float* out = (float*)d_out;

    cudaFuncSetAttribute(layer_fused2, cudaFuncAttributeMaxDynamicSharedMemorySize, FSMEM);
    cudaFuncSetAttribute(gemm_out_tc, cudaFuncAttributeMaxDynamicSharedMemorySize, SMEM_BYTES);

    conv_wqkv16<<<WROWS, 256>>>(qw, kw, vw);
    conv_wout16<<<Vn, 256>>>(ow);
    embed_kernel<<<Mr, 256>>>(inputs, tok, pe);

    for (int l = 0; l < Ln; l++) {
        layer_fused2<<<dim3(64, 16), 256, FSMEM>>>(
            l & 1, l, qb + (size_t)l * Dm, kb + (size_t)l * Dm, vb + (size_t)l * Dm);
    }
    gemm_out_tc<<<dim3(48, 250), 256, SMEM_BYTES>>>(ob, out);
}

// round 16
// speedup vs baseline: 1.2663x; 1.2230x over previous
#include <cuda_runtime.h>
#include <cuda_fp16.h>
#include <cstdint>

constexpr int S  = 24;
constexpr int Bn = 256;
constexpr int Dm = 1024;
constexpr int Ln = 12;
constexpr int Vn = 32000;
constexpr int Mr = S * Bn;          // 6144
constexpr int WROWS = Ln * 3 * Dm;  // 36864

// logits GEMM (proven 128x128 core)
constexpr int BM = 128, BN = 128, BK = 64, STAGES = 3;
constexpr int STAGE_BYTES = (BM * BK + BN * BK) * 2;      // 32 KB
constexpr int SMEM_BYTES  = STAGES * STAGE_BYTES;         // 96 KB

// fused layer kernel: 96x192 tile
constexpr int FST_BYTES = (96 * 64 + 192 * 64) * 2;       // 36864
constexpr int FSMEM = 3 * FST_BYTES;                      // 110592

// ---------------- scratch (device globals; no allocation) ----------------
// x rows are [b][s]: row = b*24 + s
__device__ float g_x[(size_t)Mr * Dm];
__device__ uint16_t g_xh16a[(size_t)Mr * Dm];  // fp16 x ping
__device__ uint16_t g_xh16b[(size_t)Mr * Dm];  // fp16 x pong
__device__ uint16_t g_w16[(size_t)WROWS * Dm]; // [l][h][q64|k64|v64][1024]
__device__ uint16_t g_ow16[(size_t)Vn * Dm];   // fp16 out_w

__device__ __forceinline__ uint32_t smem_u32(const void* p) {
    uint32_t a;
    asm("{ .reg .u64 t; cvta.to.shared.u64 t, %1; cvt.u32.u64 %0, t; }" : "=r"(a) : "l"(p));
    return a;
}

// xor swizzle for 128-byte rows: 16B chunk index xored with row%8
__device__ __forceinline__ uint32_t swz(int row, int g) {
    return (uint32_t)(row * 128 + ((g ^ (row & 7)) << 4));
}

__device__ __forceinline__ uint32_t packh2(float a, float b) {
    __half2 h = __floats2half2_rn(a, b);
    return *reinterpret_cast<uint32_t*>(&h);
}

#define MMA16816(d, a, b)                                                     \
    asm volatile(                                                             \
        "mma.sync.aligned.m16n8k16.row.col.f32.f16.f16.f32 "                  \
        "{%0,%1,%2,%3}, {%4,%5,%6,%7}, {%8,%9}, {%0,%1,%2,%3};"               \
        : "+f"((d)[0]), "+f"((d)[1]), "+f"((d)[2]), "+f"((d)[3])              \
        : "r"((a)[0]), "r"((a)[1]), "r"((a)[2]), "r"((a)[3]),                 \
          "r"((b)[0]), "r"((b)[1]))

// ---------------------------------------------------------------------------
// Fused layer kernel: grid (64 mT, 16 h), 256 threads (8 warps: 2m x 4n).
//   GEMM:  [96 rows of x] . [q|k|v weight slice of head h]^T -> 96x192
//   then MMA-based attention for 4 batches + residual + fp16 convert.
// ---------------------------------------------------------------------------
__global__ void __launch_bounds__(256, 2) layer_fused2(
    int parity, int layer,
    const float* __restrict__ qb, const float* __restrict__ kb,
    const float* __restrict__ vb)
{
    extern __shared__ char smem[];
    const uint32_t sb = smem_u32(smem);
    const int tid = threadIdx.x;
    const int lane = tid & 31;
    const int wid = tid >> 5;
    const int wm = wid & 1;
    const int wn = wid >> 1;
    const int mT = blockIdx.x;
    const int h  = blockIdx.y;

    const uint16_t* Xin = parity ? g_xh16b : g_xh16a;
    uint16_t* Xout      = parity ? g_xh16a : g_xh16b;
    const uint16_t* A = Xin + (size_t)mT * 96 * Dm;
    const uint16_t* W = g_w16 + ((size_t)layer * 16 + h) * 192 * Dm;

    auto loadStage = [&](int it, int slot) {
        const int k0 = it * 64;
        const uint32_t sa = sb + slot * FST_BYTES;
        const uint32_t sw = sa + 96 * 64 * 2;
#pragma unroll
        for (int i = 0; i < 3; i++) {              // A: 768 16B chunks
            int ch = tid + i * 256;
            int r = ch >> 3, cb = ch & 7;
            const void* gp = A + (size_t)r * Dm + k0 + cb * 8;
            asm volatile("cp.async.cg.shared.global [%0], [%1], 16;"
                         :: "r"(sa + swz(r, cb)), "l"(gp));
        }
#pragma unroll
        for (int i = 0; i < 6; i++) {              // W: 1536 16B chunks
            int ch = tid + i * 256;
            int r = ch >> 3, cb = ch & 7;
            const void* gp = W + (size_t)r * Dm + k0 + cb * 8;
            asm volatile("cp.async.cg.shared.global [%0], [%1], 16;"
                         :: "r"(sw + swz(r, cb)), "l"(gp));
        }
        asm volatile("cp.async.commit_group;");
    };

    float acc[3][6][4];
#pragma unroll
    for (int a = 0; a < 3; a++)
#pragma unroll
        for (int b = 0; b < 6; b++)
#pragma unroll
            for (int c = 0; c < 4; c++) acc[a][b][c] = 0.f;

    loadStage(0, 0);
    loadStage(1, 1);

    for (int it = 0; it < 16; it++) {
        if (it + 2 < 16) asm volatile("cp.async.wait_group 1;");
        else             asm volatile("cp.async.wait_group 0;");
        __syncthreads();
        if (it + 2 < 16) loadStage(it + 2, (it + 2) % 3);

        const uint32_t sa = sb + (it % 3) * FST_BYTES;
        const uint32_t sw = sa + 96 * 64 * 2;
#pragma unroll
        for (int q = 0; q < 4; q++) {
            uint32_t afr[3][4], bfr[6][2];
#pragma unroll
            for (int mi = 0; mi < 3; mi++) {
                int m = wm * 48 + mi * 16 + (lane & 15);
                int g = 2 * q + (lane >> 4);
                asm volatile("ldmatrix.sync.aligned.m8n8.x4.shared.b16 {%0,%1,%2,%3}, [%4];"
                             : "=r"(afr[mi][0]), "=r"(afr[mi][1]),
                               "=r"(afr[mi][2]), "=r"(afr[mi][3])
                             : "r"(sa + swz(m, g)));
            }
#pragma unroll
            for (int njp = 0; njp < 3; njp++) {
                int n = wn * 48 + njp * 16 + (lane & 7) + ((lane & 16) >> 1);
                int g = 2 * q + ((lane >> 3) & 1);
                asm volatile("ldmatrix.sync.aligned.m8n8.x4.shared.b16 {%0,%1,%2,%3}, [%4];"
                             : "=r"(bfr[2 * njp][0]), "=r"(bfr[2 * njp][1]),
                               "=r"(bfr[2 * njp + 1][0]), "=r"(bfr[2 * njp + 1][1])
                             : "r"(sw + swz(n, g)));
            }
#pragma unroll
            for (int mi = 0; mi < 3; mi++)
#pragma unroll
                for (int nj = 0; nj < 6; nj++)
                    MMA16816(acc[mi][nj], afr[mi], bfr[nj]);
        }
    }
    __syncthreads();   // all warps done with stage smem; reuse it below

    // ---- epilogue smem: fp16 Q/K/V in [4][32][64] batch-padded, swizzled ----
    // offsets (bytes from smem base): Q 0, K 16384, V 32768 (48KB total)
    // zero pad rows 24..31 of all three arrays (safety for Q, required for V)
    for (int p = tid; p < 768; p += 256) {       // 768 uint4 = 12KB
        int arr = p / 256;
        int q4  = p - arr * 256;                 // batch(2b) row(3b) chunk(3b)
        int bb  = q4 >> 6;
        int rr  = 24 + ((q4 >> 3) & 7);
        int ch  = q4 & 7;
        *reinterpret_cast<uint4*>(smem + arr * 16384 + (bb * 32 + rr) * 128 + ch * 16)
            = make_uint4(0, 0, 0, 0);
    }

    // scatter q/k/v (+bias) to smem as fp16
    {
        const int rl = lane >> 2;
        const int cl = 2 * (lane & 3);
#pragma unroll
        for (int mi = 0; mi < 3; mi++)
#pragma unroll
            for (int ro = 0; ro < 2; ro++) {
                int row = wm * 48 + mi * 16 + ro * 8 + rl;   // 0..95
                int bb = row / 24;
                int si = row - bb * 24;
                int srow = bb * 32 + si;
#pragma unroll
                for (int nj = 0; nj < 6; nj++) {
                    int c = wn * 48 + nj * 8 + cl;
                    int mat = c >> 6;
                    int cc = c & 63;
                    const float* bp = (mat == 0) ? qb : (mat == 1) ? kb : vb;
                    float v0 = acc[mi][nj][ro * 2 + 0] + bp[h * 64 + cc];
                    float v1 = acc[mi][nj][ro * 2 + 1] + bp[h * 64 + cc + 1];
                    uint32_t off = (uint32_t)mat * 16384 + swz(srow, cc >> 3)
                                   + (cc & 7) * 2;
                    *reinterpret_cast<__half2*>(smem + off) = __floats2half2_rn(v0, v1);
                }
            }
    }
    __syncthreads();

    // ---- MMA attention: warps 0-3, one batch each ----
    if (wid < 4) {
        const int bb = wid;
        const uint32_t qB = sb + bb * 32 * 128;
        const uint32_t kB = sb + 16384 + bb * 32 * 128;
        const uint32_t vB = sb + 32768 + bb * 32 * 128;
        const int g = lane >> 2;
        const int t = lane & 3;

        // scores: m32 (2 m16) x n24 (3 n8) x k64 (4 k16)
        float sacc[2][3][4];
#pragma unroll
        for (int a = 0; a < 2; a++)
#pragma unroll
            for (int b = 0; b < 3; b++)
#pragma unroll
                for (int c = 0; c < 4; c++) sacc[a][b][c] = 0.f;

#pragma unroll
        for (int q = 0; q < 4; q++) {
            uint32_t af[2][4];
#pragma unroll
            for (int mi = 0; mi < 2; mi++)
                asm volatile("ldmatrix.sync.aligned.m8n8.x4.shared.b16 {%0,%1,%2,%3}, [%4];"
                             : "=r"(af[mi][0]), "=r"(af[mi][1]),
                               "=r"(af[mi][2]), "=r"(af[mi][3])
                             : "r"(qB + swz(mi * 16 + (lane & 15), 2 * q + (lane >> 4))));
            uint32_t bf[4][2];
#pragma unroll
            for (int hN = 0; hN < 2; hN++) {
                int n = hN * 16 + (lane & 7) + ((lane & 16) >> 1);
                int gc = 2 * q + ((lane >> 3) & 1);
                asm volatile("ldmatrix.sync.aligned.m8n8.x4.shared.b16 {%0,%1,%2,%3}, [%4];"
                             : "=r"(bf[2 * hN][0]), "=r"(bf[2 * hN][1]),
                               "=r"(bf[2 * hN + 1][0]), "=r"(bf[2 * hN + 1][1])
                             : "r"(kB + swz(n, gc)));
            }
#pragma unroll
            for (int mi = 0; mi < 2; mi++)
#pragma unroll
                for (int nj = 0; nj < 3; nj++)    // tile 3 = pad cols, skipped
                    MMA16816(sacc[mi][nj], af[mi], bf[nj]);
        }

        // softmax in registers + pack P into fp16 A-frags
        constexpr float scale = 0.03125f;   // 1/sqrt(1024)
        uint32_t sFr[2][2][4];              // [mi][k16step][4]
#pragma unroll
        for (int mi = 0; mi < 2; mi++) {
            float vA[6], vB2[6];
#pragma unroll
            for (int nj = 0; nj < 3; nj++) {
                vA[2 * nj]      = sacc[mi][nj][0] * scale;
                vA[2 * nj + 1]  = sacc[mi][nj][1] * scale;
                vB2[2 * nj]     = sacc[mi][nj][2] * scale;
                vB2[2 * nj + 1] = sacc[mi][nj][3] * scale;
            }
            float mA = vA[0], mB = vB2[0];
#pragma unroll
            for (int j = 1; j < 6; j++) { mA = fmaxf(mA, vA[j]); mB = fmaxf(mB, vB2[j]); }
            mA = fmaxf(mA, __shfl_xor_sync(0xFFFFFFFFu, mA, 1));
            mA = fmaxf(mA, __shfl_xor_sync(0xFFFFFFFFu, mA, 2));
            mB = fmaxf(mB, __shfl_xor_sync(0xFFFFFFFFu, mB, 1));
            mB = fmaxf(mB, __shfl_xor_sync(0xFFFFFFFFu, mB, 2));
            float sA = 0.f, sB = 0.f;
#pragma unroll
            for (int j = 0; j < 6; j++) {
                vA[j] = expf(vA[j] - mA);  sA += vA[j];
                vB2[j] = expf(vB2[j] - mB); sB += vB2[j];
            }
            sA += __shfl_xor_sync(0xFFFFFFFFu, sA, 1);
            sA += __shfl_xor_sync(0xFFFFFFFFu, sA, 2);
            sB += __shfl_xor_sync(0xFFFFFFFFu, sB, 1);
            sB += __shfl_xor_sync(0xFFFFFFFFu, sB, 2);
            float iA = 1.f / sA, iB = 1.f / sB;
#pragma unroll
            for (int j = 0; j < 6; j++) { vA[j] *= iA; vB2[j] *= iB; }
            // k16 step 0: S cols 0-15 (tiles 0,1); step 1: cols 16-23 (tile 2) + zero pad
            sFr[mi][0][0] = packh2(vA[0], vA[1]);
            sFr[mi][0][1] = packh2(vB2[0], vB2[1]);
            sFr[mi][0][2] = packh2(vA[2], vA[3]);
            sFr[mi][0][3] = packh2(vB2[2], vB2[3]);
            sFr[mi][1][0] = packh2(vA[4], vA[5]);
            sFr[mi][1][1] = packh2(vB2[4], vB2[5]);
            sFr[mi][1][2] = 0u;
            sFr[mi][1][3] = 0u;
        }

        // AV: m32 x n64 (8 n8) x k24 (2 k16, second padded with zeros)
        float oacc[2][8][4];
#pragma unroll
        for (int a = 0; a < 2; a++)
#pragma unroll
            for (int b = 0; b < 8; b++)
#pragma unroll
                for (int c = 0; c < 4; c++) oacc[a][b][c] = 0.f;

#pragma unroll
        for (int ks = 0; ks < 2; ks++) {
            uint32_t vf[8][2];
#pragma unroll
            for (int nb = 0; nb < 4; nb++)
                asm volatile("ldmatrix.sync.aligned.m8n8.x4.trans.shared.b16 {%0,%1,%2,%3}, [%4];"
                             : "=r"(vf[2 * nb][0]), "=r"(vf[2 * nb][1]),
                               "=r"(vf[2 * nb + 1][0]), "=r"(vf[2 * nb + 1][1])
                             : "r"(vB + swz(ks * 16 + (lane & 15), 2 * nb + (lane >> 4))));
#pragma unroll
            for (int mi = 0; mi < 2; mi++)
#pragma unroll
                for (int nj = 0; nj < 8; nj++)
                    MMA16816(oacc[mi][nj], sFr[mi][ks], vf[nj]);
        }

        // store: residual on g_x + fp16 Xout (valid rows 0-23 only)
#pragma unroll
        for (int mi = 0; mi < 2; mi++)
#pragma unroll
            for (int hf = 0; hf < 2; hf++) {
                int row = mi * 16 + hf * 8 + g;
                if (mi == 1 && hf == 1) continue;      // rows 24-31 = pad
                int rg = mT * 96 + bb * 24 + row;
                size_t base2 = (size_t)rg * Dm + h * 64;
#pragma unroll
                for (int nj = 0; nj < 8; nj++) {
                    int d = nj * 8 + 2 * t;
                    float2 xv = *reinterpret_cast<const float2*>(g_x + base2 + d);
                    xv.x += oacc[mi][nj][hf * 2 + 0];
                    xv.y += oacc[mi][nj][hf * 2 + 1];
                    *reinterpret_cast<float2*>(g_x + base2 + d) = xv;
                    *reinterpret_cast<__half2*>(Xout + base2 + d) =
                        __floats2half2_rn(xv.x, xv.y);
                }
            }
    }
}

// ---------------------------------------------------------------------------
// Logits GEMM (128x128 proven core; A rows are [b][s], output rows [s][b])
// ---------------------------------------------------------------------------
__global__ void __launch_bounds__(256, 2) gemm_out_tc(
    const float* __restrict__ ob, float* __restrict__ out)
{
    const int mT = blockIdx.x, nT = blockIdx.y;
    const uint16_t* A = g_xh16a + (size_t)mT * 128 * Dm;
    const uint16_t* W = g_ow16 + (size_t)nT * 128 * Dm;
    const float* bias = ob + nT * 128;

    extern __shared__ char smem[];
    const uint32_t sb = smem_u32(smem);
    const int tid = threadIdx.x;
    const int lane = tid & 31;
    const int wid = tid >> 5;
    const int wm = wid & 3;
    const int wn = wid >> 2;

    auto loadStage = [&](int it, int slot) {
        const int k0 = it * BK;
        const uint32_t sa = sb + slot * STAGE_BYTES;
        const uint32_t sw = sa + BM * BK * 2;
#pragma unroll
        for (int i = 0; i < 4; i++) {
            int ch = tid + i * 256;
            int r = ch >> 3, cb = ch & 7;
            const void* gp = A + (size_t)r * Dm + k0 + cb * 8;
            asm volatile("cp.async.cg.shared.global [%0], [%1], 16;"
                         :: "r"(sa + swz(r, cb)), "l"(gp));
        }
#pragma unroll
        for (int i = 0; i < 4; i++) {
            int ch = tid + i * 256;
            int r = ch >> 3, cb = ch & 7;
            const void* gp = W + (size_t)r * Dm + k0 + cb * 8;
            asm volatile("cp.async.cg.shared.global [%0], [%1], 16;"
                         :: "r"(sw + swz(r, cb)), "l"(gp));
        }
        asm volatile("cp.async.commit_group;");
    };

    float acc[2][8][4];
#pragma unroll
    for (int a = 0; a < 2; a++)
#pragma unroll
        for (int b = 0; b < 8; b++)
#pragma unroll
            for (int c = 0; c < 4; c++) acc[a][b][c] = 0.f;

    loadStage(0, 0);
    loadStage(1, 1);

    for (int it = 0; it < 16; it++) {
        if (it + 2 < 16) asm volatile("cp.async.wait_group 1;");
        else             asm volatile("cp.async.wait_group 0;");
        __syncthreads();
        if (it + 2 < 16) loadStage(it + 2, (it + 2) % STAGES);

        const uint32_t sa = sb + (it % STAGES) * STAGE_BYTES;
        const uint32_t sw = sa + BM * BK * 2;
#pragma unroll
        for (int q = 0; q < 4; q++) {
            uint32_t afr[2][4], bfr[8][2];
#pragma unroll
            for (int mi = 0; mi < 2; mi++) {
                int m = wm * 32 + mi * 16 + (lane & 15);
                int g = 2 * q + (lane >> 4);
                asm volatile("ldmatrix.sync.aligned.m8n8.x4.shared.b16 {%0,%1,%2,%3}, [%4];"
                             : "=r"(afr[mi][0]), "=r"(afr[mi][1]),
                               "=r"(afr[mi][2]), "=r"(afr[mi][3])
                             : "r"(sa + swz(m, g)));
            }
#pragma unroll
            for (int nj = 0; nj < 8; nj += 2) {
                int n = wn * 64 + nj * 8 + (lane & 7) + ((lane & 16) >> 1);
                int g = 2 * q + ((lane >> 3) & 1);
                asm volatile("ldmatrix.sync.aligned.m8n8.x4.shared.b16 {%0,%1,%2,%3}, [%4];"
                             : "=r"(bfr[nj][0]), "=r"(bfr[nj][1]),
                               "=r"(bfr[nj + 1][0]), "=r"(bfr[nj + 1][1])
                             : "r"(sw + swz(n, g)));
            }
#pragma unroll
            for (int mi = 0; mi < 2; mi++)
#pragma unroll
                for (int nj = 0; nj < 8; nj++)
                    MMA16816(acc[mi][nj], afr[mi], bfr[nj]);
        }
    }

    const int r0 = wm * 32 + (lane >> 2);
    const int cl = 2 * (lane & 3);
#pragma unroll
    for (int mi = 0; mi < 2; mi++)
#pragma unroll
        for (int ro = 0; ro < 2; ro++) {
            int rg = mT * 128 + r0 + mi * 16 + ro * 8;     // [b][s] row
            int bb = rg / 24, ss = rg - bb * 24;
            float* crow = out + ((size_t)ss * Bn + bb) * Vn;
#pragma unroll
            for (int nj = 0; nj < 8; nj++) {
                int col = wn * 64 + nj * 8 + cl;
                float2 o;
                o.x = acc[mi][nj][ro * 2 + 0] + bias[col];
                o.y = acc[mi][nj][ro * 2 + 1] + bias[col + 1];
                *reinterpret_cast<float2*>(crow + nT * 128 + col) = o;
            }
        }
}

// ---------------------------------------------------------------------------
// Weight prep: qkv -> [l][h][q64|k64|v64][1024] fp16;  out_w -> fp16
// ---------------------------------------------------------------------------
__global__ void conv_wqkv16(const float* __restrict__ qw, const float* __restrict__ kw,
                            const float* __restrict__ vw) {
    size_t t = (size_t)blockIdx.x * 256 + threadIdx.x;
    size_t e = t * 4;
    int row = (int)(e >> 10);        // dest row in [l][h][192]
    int col = (int)(e & 1023);
    int l    = row / 3072;
    int rem  = row - l * 3072;
    int hh   = rem / 192;
    int rem2 = rem - hh * 192;
    int mat  = rem2 >> 6;
    int n    = hh * 64 + (rem2 & 63);
    const float* src = ((mat == 0) ? qw : (mat == 1) ? kw : vw)
                       + (((size_t)l * 1024 + n) << 10) + col;
    float4 v = *reinterpret_cast<const float4*>(src);
    size_t d = ((size_t)row << 10) + col;
    *reinterpret_cast<__half2*>(g_w16 + d)     = __floats2half2_rn(v.x, v.y);
    *reinterpret_cast<__half2*>(g_w16 + d + 2) = __floats2half2_rn(v.z, v.w);
}

__global__ void conv_wout16(const float* __restrict__ ow) {
    size_t e = ((size_t)blockIdx.x * 256 + threadIdx.x) * 4;
    float4 v = *reinterpret_cast<const float4*>(ow + e);
    *reinterpret_cast<__half2*>(g_ow16 + e)     = __floats2half2_rn(v.x, v.y);
    *reinterpret_cast<__half2*>(g_ow16 + e + 2) = __floats2half2_rn(v.z, v.w);
}

// ---------------------------------------------------------------------------
// Embedding into [b][s] layout + fp16 convert (buffer A)
// ---------------------------------------------------------------------------
__global__ void embed_kernel(const int* __restrict__ inputs,
                             const float* __restrict__ tok,
                             const float* __restrict__ pe) {
    int row = blockIdx.x;            // b*24 + s
    int b = row / 24;
    int s = row - b * 24;
    int t = inputs[s * Bn + b];
    const float4* te = reinterpret_cast<const float4*>(tok + (size_t)t * Dm);
    const float4* pp = reinterpret_cast<const float4*>(pe + (size_t)s * Dm);
    float4 a = te[threadIdx.x];
    float4 bp = pp[threadIdx.x];
    float4 o = make_float4(a.x + bp.x, a.y + bp.y, a.z + bp.z, a.w + bp.w);
    size_t d = (size_t)row * Dm + threadIdx.x * 4;
    *reinterpret_cast<float4*>(g_x + d) = o;
    *reinterpret_cast<__half2*>(g_xh16a + d)     = __floats2half2_rn(o.x, o.y);
    *reinterpret_cast<__half2*>(g_xh16a + d + 2) = __floats2half2_rn(o.z, o.w);
}

// ---------------------------------------------------------------------------
extern "C" void kernel_launch(void* const* d_in, const int* in_sizes, int n_in,
                              void* d_out, int out_size) {
    const int*   inputs = (const int*)d_in[0];
    // d_in[1] = mask (reference drops it)
    const float* tok = (const float*)d_in[2];
    const float* pe  = (const float*)d_in[3];
    const float* qw  = (const float*)d_in[4];
    const float* qb  = (const float*)d_in[5];
    const float* kw  = (const float*)d_in[6];
    const float* kb  = (const float*)d_in[7];
    const float* vw  = (const float*)d_in[8];
    const float* vb  = (const float*)d_in[9];
    const float* ow  = (const float*)d_in[10];
    const float* ob  = (const float*)d_in[11];
    float* out = (float*)d_out;

    cudaFuncSetAttribute(layer_fused2, cudaFuncAttributeMaxDynamicSharedMemorySize, FSMEM);
    cudaFuncSetAttribute(gemm_out_tc, cudaFuncAttributeMaxDynamicSharedMemorySize, SMEM_BYTES);

    conv_wqkv16<<<WROWS, 256>>>(qw, kw, vw);
    conv_wout16<<<Vn, 256>>>(ow);
    embed_kernel<<<Mr, 256>>>(inputs, tok, pe);

    for (int l = 0; l < Ln; l++) {
        layer_fused2<<<dim3(64, 16), 256, FSMEM>>>(
            l & 1, l, qb + (size_t)l * Dm, kb + (size_t)l * Dm, vb + (size_t)l * Dm);
    }
    gemm_out_tc<<<dim3(48, 250), 256, SMEM_BYTES>>>(ob, out);
}

// round 17
// speedup vs baseline: 1.2782x; 1.0094x over previous
#include <cuda_runtime.h>
#include <cuda_fp16.h>
#include <cstdint>

constexpr int S  = 24;
constexpr int Bn = 256;
constexpr int Dm = 1024;
constexpr int Ln = 12;
constexpr int Vn = 32000;
constexpr int Mr = S * Bn;          // 6144
constexpr int WROWS = Ln * 3 * Dm;  // 36864

// logits GEMM (proven 128x128 core)
constexpr int BM = 128, BN = 128, BK = 64, STAGES = 3;
constexpr int STAGE_BYTES = (BM * BK + BN * BK) * 2;      // 32 KB
constexpr int SMEM_BYTES  = STAGES * STAGE_BYTES;         // 96 KB

// fused layer kernel: 96x192 tile
constexpr int FST_BYTES = (96 * 64 + 192 * 64) * 2;       // 36864
constexpr int FSMEM = 3 * FST_BYTES;                      // 110592

// ---------------- scratch (device globals; no allocation) ----------------
// x rows are [b][s]: row = b*24 + s
__device__ float g_x[(size_t)Mr * Dm];
__device__ uint16_t g_xh16a[(size_t)Mr * Dm];  // fp16 x ping
__device__ uint16_t g_xh16b[(size_t)Mr * Dm];  // fp16 x pong
__device__ uint16_t g_w16[(size_t)WROWS * Dm]; // [l][h][q64|k64|v64][1024]
__device__ uint16_t g_ow16[(size_t)Vn * Dm];   // fp16 out_w

__device__ __forceinline__ uint32_t smem_u32(const void* p) {
    uint32_t a;
    asm("{ .reg .u64 t; cvta.to.shared.u64 t, %1; cvt.u32.u64 %0, t; }" : "=r"(a) : "l"(p));
    return a;
}

// xor swizzle for 128-byte rows: 16B chunk index xored with row%8
__device__ __forceinline__ uint32_t swz(int row, int g) {
    return (uint32_t)(row * 128 + ((g ^ (row & 7)) << 4));
}

__device__ __forceinline__ uint32_t packh2(float a, float b) {
    __half2 h = __floats2half2_rn(a, b);
    return *reinterpret_cast<uint32_t*>(&h);
}

#define MMA16816(d, a, b)                                                     \
    asm volatile(                                                             \
        "mma.sync.aligned.m16n8k16.row.col.f32.f16.f16.f32 "                  \
        "{%0,%1,%2,%3}, {%4,%5,%6,%7}, {%8,%9}, {%0,%1,%2,%3};"               \
        : "+f"((d)[0]), "+f"((d)[1]), "+f"((d)[2]), "+f"((d)[3])              \
        : "r"((a)[0]), "r"((a)[1]), "r"((a)[2]), "r"((a)[3]),                 \
          "r"((b)[0]), "r"((b)[1]))

// ---------------------------------------------------------------------------
// Fused layer kernel: grid (64 mT, 16 h), 256 threads (8 warps: 2m x 4n).
//   GEMM:  [96 rows of x] . [q|k|v weight slice of head h]^T -> 96x192
//   then MMA attention: 8 warps = 4 batches x 2 m-halves.
// ---------------------------------------------------------------------------
__global__ void __launch_bounds__(256, 2) layer_fused2(
    int parity, int layer,
    const float* __restrict__ qb, const float* __restrict__ kb,
    const float* __restrict__ vb)
{
    extern __shared__ char smem[];
    const uint32_t sb = smem_u32(smem);
    const int tid = threadIdx.x;
    const int lane = tid & 31;
    const int wid = tid >> 5;
    const int wm = wid & 1;
    const int wn = wid >> 1;
    const int mT = blockIdx.x;
    const int h  = blockIdx.y;

    const uint16_t* Xin = parity ? g_xh16b : g_xh16a;
    uint16_t* Xout      = parity ? g_xh16a : g_xh16b;
    const uint16_t* A = Xin + (size_t)mT * 96 * Dm;
    const uint16_t* W = g_w16 + ((size_t)layer * 16 + h) * 192 * Dm;

    auto loadStage = [&](int it, int slot) {
        const int k0 = it * 64;
        const uint32_t sa = sb + slot * FST_BYTES;
        const uint32_t sw = sa + 96 * 64 * 2;
#pragma unroll
        for (int i = 0; i < 3; i++) {              // A: 768 16B chunks
            int ch = tid + i * 256;
            int r = ch >> 3, cb = ch & 7;
            const void* gp = A + (size_t)r * Dm + k0 + cb * 8;
            asm volatile("cp.async.cg.shared.global [%0], [%1], 16;"
                         :: "r"(sa + swz(r, cb)), "l"(gp));
        }
#pragma unroll
        for (int i = 0; i < 6; i++) {              // W: 1536 16B chunks
            int ch = tid + i * 256;
            int r = ch >> 3, cb = ch & 7;
            const void* gp = W + (size_t)r * Dm + k0 + cb * 8;
            asm volatile("cp.async.cg.shared.global [%0], [%1], 16;"
                         :: "r"(sw + swz(r, cb)), "l"(gp));
        }
        asm volatile("cp.async.commit_group;");
    };

    float acc[3][6][4];
#pragma unroll
    for (int a = 0; a < 3; a++)
#pragma unroll
        for (int b = 0; b < 6; b++)
#pragma unroll
            for (int c = 0; c < 4; c++) acc[a][b][c] = 0.f;

    loadStage(0, 0);
    loadStage(1, 1);

    for (int it = 0; it < 16; it++) {
        if (it + 2 < 16) asm volatile("cp.async.wait_group 1;");
        else             asm volatile("cp.async.wait_group 0;");
        __syncthreads();
        if (it + 2 < 16) loadStage(it + 2, (it + 2) % 3);

        const uint32_t sa = sb + (it % 3) * FST_BYTES;
        const uint32_t sw = sa + 96 * 64 * 2;
#pragma unroll
        for (int q = 0; q < 4; q++) {
            uint32_t afr[3][4], bfr[6][2];
#pragma unroll
            for (int mi = 0; mi < 3; mi++) {
                int m = wm * 48 + mi * 16 + (lane & 15);
                int g = 2 * q + (lane >> 4);
                asm volatile("ldmatrix.sync.aligned.m8n8.x4.shared.b16 {%0,%1,%2,%3}, [%4];"
                             : "=r"(afr[mi][0]), "=r"(afr[mi][1]),
                               "=r"(afr[mi][2]), "=r"(afr[mi][3])
                             : "r"(sa + swz(m, g)));
            }
#pragma unroll
            for (int njp = 0; njp < 3; njp++) {
                int n = wn * 48 + njp * 16 + (lane & 7) + ((lane & 16) >> 1);
                int g = 2 * q + ((lane >> 3) & 1);
                asm volatile("ldmatrix.sync.aligned.m8n8.x4.shared.b16 {%0,%1,%2,%3}, [%4];"
                             : "=r"(bfr[2 * njp][0]), "=r"(bfr[2 * njp][1]),
                               "=r"(bfr[2 * njp + 1][0]), "=r"(bfr[2 * njp + 1][1])
                             : "r"(sw + swz(n, g)));
            }
#pragma unroll
            for (int mi = 0; mi < 3; mi++)
#pragma unroll
                for (int nj = 0; nj < 6; nj++)
                    MMA16816(acc[mi][nj], afr[mi], bfr[nj]);
        }
    }
    __syncthreads();   // all warps done with stage smem; reuse it below

    // ---- epilogue smem: fp16 Q/K/V in [4][32][64] batch-padded, swizzled ----
    // offsets (bytes from smem base): Q 0, K 16384, V 32768 (48KB total)
    // zero pad rows 24..31 of all three arrays
    for (int p = tid; p < 768; p += 256) {       // 768 uint4 = 12KB
        int arr = p / 256;
        int q4  = p - arr * 256;
        int bb  = q4 >> 6;
        int rr  = 24 + ((q4 >> 3) & 7);
        int ch  = q4 & 7;
        *reinterpret_cast<uint4*>(smem + arr * 16384 + (bb * 32 + rr) * 128 + ch * 16)
            = make_uint4(0, 0, 0, 0);
    }

    // scatter q/k/v (+bias) to smem as fp16
    {
        const int rl = lane >> 2;
        const int cl = 2 * (lane & 3);
#pragma unroll
        for (int mi = 0; mi < 3; mi++)
#pragma unroll
            for (int ro = 0; ro < 2; ro++) {
                int row = wm * 48 + mi * 16 + ro * 8 + rl;   // 0..95
                int bb = row / 24;
                int si = row - bb * 24;
                int srow = bb * 32 + si;
#pragma unroll
                for (int nj = 0; nj < 6; nj++) {
                    int c = wn * 48 + nj * 8 + cl;
                    int mat = c >> 6;
                    int cc = c & 63;
                    const float* bp = (mat == 0) ? qb : (mat == 1) ? kb : vb;
                    float v0 = acc[mi][nj][ro * 2 + 0] + bp[h * 64 + cc];
                    float v1 = acc[mi][nj][ro * 2 + 1] + bp[h * 64 + cc + 1];
                    uint32_t off = (uint32_t)mat * 16384 + swz(srow, cc >> 3)
                                   + (cc & 7) * 2;
                    *reinterpret_cast<__half2*>(smem + off) = __floats2half2_rn(v0, v1);
                }
            }
    }
    __syncthreads();

    // ---- MMA attention: 8 warps = (batch = wid>>1, m-half = wid&1) ----
    {
        const int bb = wid >> 1;
        const int mh = wid & 1;
        const uint32_t qB = sb + bb * 32 * 128;
        const uint32_t kB = sb + 16384 + bb * 32 * 128;
        const uint32_t vB = sb + 32768 + bb * 32 * 128;
        const int g = lane >> 2;
        const int t = lane & 3;

        // scores: m16 x n24 (3 n8) x k64 (4 k16)
        float sacc[3][4];
#pragma unroll
        for (int b = 0; b < 3; b++)
#pragma unroll
            for (int c = 0; c < 4; c++) sacc[b][c] = 0.f;

#pragma unroll
        for (int q = 0; q < 4; q++) {
            uint32_t af[4];
            asm volatile("ldmatrix.sync.aligned.m8n8.x4.shared.b16 {%0,%1,%2,%3}, [%4];"
                         : "=r"(af[0]), "=r"(af[1]), "=r"(af[2]), "=r"(af[3])
                         : "r"(qB + swz(mh * 16 + (lane & 15), 2 * q + (lane >> 4))));
            uint32_t bf[4][2];
#pragma unroll
            for (int hN = 0; hN < 2; hN++) {
                int n = hN * 16 + (lane & 7) + ((lane & 16) >> 1);
                int gc = 2 * q + ((lane >> 3) & 1);
                asm volatile("ldmatrix.sync.aligned.m8n8.x4.shared.b16 {%0,%1,%2,%3}, [%4];"
                             : "=r"(bf[2 * hN][0]), "=r"(bf[2 * hN][1]),
                               "=r"(bf[2 * hN + 1][0]), "=r"(bf[2 * hN + 1][1])
                             : "r"(kB + swz(n, gc)));
            }
#pragma unroll
            for (int nj = 0; nj < 3; nj++)    // tile 3 = pad cols, skipped
                MMA16816(sacc[nj], af, bf[nj]);
        }

        // softmax in registers + pack P into fp16 A-frags
        // rows mh*16+g (vA) and mh*16+8+g (vB2); garbage rows >=24 are isolated
        constexpr float scale = 0.03125f;   // 1/sqrt(1024)
        uint32_t sFr[2][4];                  // [k16step][4]
        {
            float vA[6], vB2[6];
#pragma unroll
            for (int nj = 0; nj < 3; nj++) {
                vA[2 * nj]      = sacc[nj][0] * scale;
                vA[2 * nj + 1]  = sacc[nj][1] * scale;
                vB2[2 * nj]     = sacc[nj][2] * scale;
                vB2[2 * nj + 1] = sacc[nj][3] * scale;
            }
            float mA = vA[0], mB = vB2[0];
#pragma unroll
            for (int j = 1; j < 6; j++) { mA = fmaxf(mA, vA[j]); mB = fmaxf(mB, vB2[j]); }
            mA = fmaxf(mA, __shfl_xor_sync(0xFFFFFFFFu, mA, 1));
            mA = fmaxf(mA, __shfl_xor_sync(0xFFFFFFFFu, mA, 2));
            mB = fmaxf(mB, __shfl_xor_sync(0xFFFFFFFFu, mB, 1));
            mB = fmaxf(mB, __shfl_xor_sync(0xFFFFFFFFu, mB, 2));
            float sA = 0.f, sB = 0.f;
#pragma unroll
            for (int j = 0; j < 6; j++) {
                vA[j] = expf(vA[j] - mA);  sA += vA[j];
                vB2[j] = expf(vB2[j] - mB); sB += vB2[j];
            }
            sA += __shfl_xor_sync(0xFFFFFFFFu, sA, 1);
            sA += __shfl_xor_sync(0xFFFFFFFFu, sA, 2);
            sB += __shfl_xor_sync(0xFFFFFFFFu, sB, 1);
            sB += __shfl_xor_sync(0xFFFFFFFFu, sB, 2);
            float iA = 1.f / sA, iB = 1.f / sB;
#pragma unroll
            for (int j = 0; j < 6; j++) { vA[j] *= iA; vB2[j] *= iB; }
            sFr[0][0] = packh2(vA[0], vA[1]);
            sFr[0][1] = packh2(vB2[0], vB2[1]);
            sFr[0][2] = packh2(vA[2], vA[3]);
            sFr[0][3] = packh2(vB2[2], vB2[3]);
            sFr[1][0] = packh2(vA[4], vA[5]);
            sFr[1][1] = packh2(vB2[4], vB2[5]);
            sFr[1][2] = 0u;
            sFr[1][3] = 0u;
        }

        // AV: m16 x n64 (8 n8) x k24 (2 k16, second zero-padded)
        float oacc[8][4];
#pragma unroll
        for (int b = 0; b < 8; b++)
#pragma unroll
            for (int c = 0; c < 4; c++) oacc[b][c] = 0.f;

#pragma unroll
        for (int ks = 0; ks < 2; ks++) {
            uint32_t vf[8][2];
#pragma unroll
            for (int nb = 0; nb < 4; nb++)
                asm volatile("ldmatrix.sync.aligned.m8n8.x4.trans.shared.b16 {%0,%1,%2,%3}, [%4];"
                             : "=r"(vf[2 * nb][0]), "=r"(vf[2 * nb][1]),
                               "=r"(vf[2 * nb + 1][0]), "=r"(vf[2 * nb + 1][1])
                             : "r"(vB + swz(ks * 16 + (lane & 15), 2 * nb + (lane >> 4))));
#pragma unroll
            for (int nj = 0; nj < 8; nj++)
                MMA16816(oacc[nj], sFr[ks], vf[nj]);
        }

        // store: residual on g_x + fp16 Xout (valid rows 0-23 only)
#pragma unroll
        for (int hf = 0; hf < 2; hf++) {
            int row = mh * 16 + hf * 8 + g;
            if (mh == 1 && hf == 1) continue;      // rows 24-31 = pad
            int rg = mT * 96 + bb * 24 + row;
            size_t base2 = (size_t)rg * Dm + h * 64;
#pragma unroll
            for (int nj = 0; nj < 8; nj++) {
                int d = nj * 8 + 2 * t;
                float2 xv = *reinterpret_cast<const float2*>(g_x + base2 + d);
                xv.x += oacc[nj][hf * 2 + 0];
                xv.y += oacc[nj][hf * 2 + 1];
                *reinterpret_cast<float2*>(g_x + base2 + d) = xv;
                *reinterpret_cast<__half2*>(Xout + base2 + d) =
                    __floats2half2_rn(xv.x, xv.y);
            }
        }
    }
}

// ---------------------------------------------------------------------------
// Logits GEMM (128x128 proven core; A rows are [b][s], output rows [s][b])
// ---------------------------------------------------------------------------
__global__ void __launch_bounds__(256, 2) gemm_out_tc(
    const float* __restrict__ ob, float* __restrict__ out)
{
    const int mT = blockIdx.x, nT = blockIdx.y;
    const uint16_t* A = g_xh16a + (size_t)mT * 128 * Dm;
    const uint16_t* W = g_ow16 + (size_t)nT * 128 * Dm;
    const float* bias = ob + nT * 128;

    extern __shared__ char smem[];
    const uint32_t sb = smem_u32(smem);
    const int tid = threadIdx.x;
    const int lane = tid & 31;
    const int wid = tid >> 5;
    const int wm = wid & 3;
    const int wn = wid >> 2;

    auto loadStage = [&](int it, int slot) {
        const int k0 = it * BK;
        const uint32_t sa = sb + slot * STAGE_BYTES;
        const uint32_t sw = sa + BM * BK * 2;
#pragma unroll
        for (int i = 0; i < 4; i++) {
            int ch = tid + i * 256;
            int r = ch >> 3, cb = ch & 7;
            const void* gp = A + (size_t)r * Dm + k0 + cb * 8;
            asm volatile("cp.async.cg.shared.global [%0], [%1], 16;"
                         :: "r"(sa + swz(r, cb)), "l"(gp));
        }
#pragma unroll
        for (int i = 0; i < 4; i++) {
            int ch = tid + i * 256;
            int r = ch >> 3, cb = ch & 7;
            const void* gp = W + (size_t)r * Dm + k0 + cb * 8;
            asm volatile("cp.async.cg.shared.global [%0], [%1], 16;"
                         :: "r"(sw + swz(r, cb)), "l"(gp));
        }
        asm volatile("cp.async.commit_group;");
    };

    float acc[2][8][4];
#pragma unroll
    for (int a = 0; a < 2; a++)
#pragma unroll
        for (int b = 0; b < 8; b++)
#pragma unroll
            for (int c = 0; c < 4; c++) acc[a][b][c] = 0.f;

    loadStage(0, 0);
    loadStage(1, 1);

    for (int it = 0; it < 16; it++) {
        if (it + 2 < 16) asm volatile("cp.async.wait_group 1;");
        else             asm volatile("cp.async.wait_group 0;");
        __syncthreads();
        if (it + 2 < 16) loadStage(it + 2, (it + 2) % STAGES);

        const uint32_t sa = sb + (it % STAGES) * STAGE_BYTES;
        const uint32_t sw = sa + BM * BK * 2;
#pragma unroll
        for (int q = 0; q < 4; q++) {
            uint32_t afr[2][4], bfr[8][2];
#pragma unroll
            for (int mi = 0; mi < 2; mi++) {
                int m = wm * 32 + mi * 16 + (lane & 15);
                int g = 2 * q + (lane >> 4);
                asm volatile("ldmatrix.sync.aligned.m8n8.x4.shared.b16 {%0,%1,%2,%3}, [%4];"
                             : "=r"(afr[mi][0]), "=r"(afr[mi][1]),
                               "=r"(afr[mi][2]), "=r"(afr[mi][3])
                             : "r"(sa + swz(m, g)));
            }
#pragma unroll
            for (int nj = 0; nj < 8; nj += 2) {
                int n = wn * 64 + nj * 8 + (lane & 7) + ((lane & 16) >> 1);
                int g = 2 * q + ((lane >> 3) & 1);
                asm volatile("ldmatrix.sync.aligned.m8n8.x4.shared.b16 {%0,%1,%2,%3}, [%4];"
                             : "=r"(bfr[nj][0]), "=r"(bfr[nj][1]),
                               "=r"(bfr[nj + 1][0]), "=r"(bfr[nj + 1][1])
                             : "r"(sw + swz(n, g)));
            }
#pragma unroll
            for (int mi = 0; mi < 2; mi++)
#pragma unroll
                for (int nj = 0; nj < 8; nj++)
                    MMA16816(acc[mi][nj], afr[mi], bfr[nj]);
        }
    }

    const int r0 = wm * 32 + (lane >> 2);
    const int cl = 2 * (lane & 3);
#pragma unroll
    for (int mi = 0; mi < 2; mi++)
#pragma unroll
        for (int ro = 0; ro < 2; ro++) {
            int rg = mT * 128 + r0 + mi * 16 + ro * 8;     // [b][s] row
            int bb = rg / 24, ss = rg - bb * 24;
            float* crow = out + ((size_t)ss * Bn + bb) * Vn;
#pragma unroll
            for (int nj = 0; nj < 8; nj++) {
                int col = wn * 64 + nj * 8 + cl;
                float2 o;
                o.x = acc[mi][nj][ro * 2 + 0] + bias[col];
                o.y = acc[mi][nj][ro * 2 + 1] + bias[col + 1];
                *reinterpret_cast<float2*>(crow + nT * 128 + col) = o;
            }
        }
}

// ---------------------------------------------------------------------------
// Weight prep: qkv -> [l][h][q64|k64|v64][1024] fp16;  out_w -> fp16
// ---------------------------------------------------------------------------
__global__ void conv_wqkv16(const float* __restrict__ qw, const float* __restrict__ kw,
                            const float* __restrict__ vw) {
    size_t t = (size_t)blockIdx.x * 256 + threadIdx.x;
    size_t e = t * 4;
    int row = (int)(e >> 10);        // dest row in [l][h][192]
    int col = (int)(e & 1023);
    int l    = row / 3072;
    int rem  = row - l * 3072;
    int hh   = rem / 192;
    int rem2 = rem - hh * 192;
    int mat  = rem2 >> 6;
    int n    = hh * 64 + (rem2 & 63);
    const float* src = ((mat == 0) ? qw : (mat == 1) ? kw : vw)
                       + (((size_t)l * 1024 + n) << 10) + col;
    float4 v = *reinterpret_cast<const float4*>(src);
    size_t d = ((size_t)row << 10) + col;
    *reinterpret_cast<__half2*>(g_w16 + d)     = __floats2half2_rn(v.x, v.y);
    *reinterpret_cast<__half2*>(g_w16 + d + 2) = __floats2half2_rn(v.z, v.w);
}

__global__ void conv_wout16(const float* __restrict__ ow) {
    size_t e = ((size_t)blockIdx.x * 256 + threadIdx.x) * 4;
    float4 v = *reinterpret_cast<const float4*>(ow + e);
    *reinterpret_cast<__half2*>(g_ow16 + e)     = __floats2half2_rn(v.x, v.y);
    *reinterpret_cast<__half2*>(g_ow16 + e + 2) = __floats2half2_rn(v.z, v.w);
}

// ---------------------------------------------------------------------------
// Embedding into [b][s] layout + fp16 convert (buffer A)
// ---------------------------------------------------------------------------
__global__ void embed_kernel(const int* __restrict__ inputs,
                             const float* __restrict__ tok,
                             const float* __restrict__ pe) {
    int row = blockIdx.x;            // b*24 + s
    int b = row / 24;
    int s = row - b * 24;
    int t = inputs[s * Bn + b];
    const float4* te = reinterpret_cast<const float4*>(tok + (size_t)t * Dm);
    const float4* pp = reinterpret_cast<const float4*>(pe + (size_t)s * Dm);
    float4 a = te[threadIdx.x];
    float4 bp = pp[threadIdx.x];
    float4 o = make_float4(a.x + bp.x, a.y + bp.y, a.z + bp.z, a.w + bp.w);
    size_t d = (size_t)row * Dm + threadIdx.x * 4;
    *reinterpret_cast<float4*>(g_x + d) = o;
    *reinterpret_cast<__half2*>(g_xh16a + d)     = __floats2half2_rn(o.x, o.y);
    *reinterpret_cast<__half2*>(g_xh16a + d + 2) = __floats2half2_rn(o.z, o.w);
}

// ---------------------------------------------------------------------------
extern "C" void kernel_launch(void* const* d_in, const int* in_sizes, int n_in,
                              void* d_out, int out_size) {
    const int*   inputs = (const int*)d_in[0];
    // d_in[1] = mask (reference drops it)
    const float* tok = (const float*)d_in[2];
    const float* pe  = (const float*)d_in[3];
    const float* qw  = (const float*)d_in[4];
    const float* qb  = (const float*)d_in[5];
    const float* kw  = (const float*)d_in[6];
    const float* kb  = (const float*)d_in[7];
    const float* vw  = (const float*)d_in[8];
    const float* vb  = (const float*)d_in[9];
    const float* ow  = (const float*)d_in[10];
    const float* ob  = (const float*)d_in[11];
    float* out = (float*)d_out;

    cudaFuncSetAttribute(layer_fused2, cudaFuncAttributeMaxDynamicSharedMemorySize, FSMEM);
    cudaFuncSetAttribute(gemm_out_tc, cudaFuncAttributeMaxDynamicSharedMemorySize, SMEM_BYTES);

    conv_wqkv16<<<WROWS, 256>>>(qw, kw, vw);
    conv_wout16<<<Vn, 256>>>(ow);
    embed_kernel<<<Mr, 256>>>(inputs, tok, pe);

    for (int l = 0; l < Ln; l++) {
        layer_fused2<<<dim3(64, 16), 256, FSMEM>>>(
            l & 1, l, qb + (size_t)l * Dm, kb + (size_t)l * Dm, vb + (size_t)l * Dm);
    }
    gemm_out_tc<<<dim3(48, 250), 256, SMEM_BYTES>>>(ob, out);
}